// round 16
// baseline (speedup 1.0000x reference)
#include <cuda_runtime.h>
#include <cuda_fp16.h>
#include <cstdint>

#define L_DIM 2048
#define D_DIM 64
#define N_BH 32
#define ROWS 128
#define JT 128
#define NJT (L_DIM / JT)
#define NTH 256

#define OFF_A 0
#define OFF_B(b) (16384 + (b) * 16384)
#define SMEM_TOTAL 49152

#define NELEM (N_BH * L_DIM * D_DIM)

__device__ __align__(16) __half g_A[NELEM];
__device__ __align__(16) __half g_B[NELEM];

__device__ __forceinline__ uint32_t smem_u32(const void* p) {
    uint32_t a;
    asm("{ .reg .u64 t; cvta.to.shared.u64 t, %1; cvt.u32.u64 %0, t; }" : "=r"(a) : "l"(p));
    return a;
}
__device__ __forceinline__ float lg2f(float x) {
    float y; asm("lg2.approx.f32 %0, %1;" : "=f"(y) : "f"(x)); return y;
}
__device__ __forceinline__ float ex2f(float x) {
    float y; asm("ex2.approx.f32 %0, %1;" : "=f"(y) : "f"(x)); return y;
}
__device__ __forceinline__ float pow23(float a) {
    return ex2f(lg2f(fmaxf(a, 0.0f)) * 0.666666667f);
}
__device__ __forceinline__ void ldsm4(uint32_t* r, uint32_t addr) {
    asm volatile("ldmatrix.sync.aligned.m8n8.x4.shared.b16 {%0,%1,%2,%3}, [%4];"
                 : "=r"(r[0]), "=r"(r[1]), "=r"(r[2]), "=r"(r[3]) : "r"(addr));
}
__device__ __forceinline__ void mma16816(float* c, const uint32_t* a, const uint32_t* b) {
    asm volatile(
        "mma.sync.aligned.m16n8k16.row.col.f32.f16.f16.f32 "
        "{%0,%1,%2,%3}, {%4,%5,%6,%7}, {%8,%9}, {%0,%1,%2,%3};"
        : "+f"(c[0]), "+f"(c[1]), "+f"(c[2]), "+f"(c[3])
        : "r"(a[0]), "r"(a[1]), "r"(a[2]), "r"(a[3]), "r"(b[0]), "r"(b[1]));
}
__device__ __forceinline__ void cpa16(uint32_t dst, const void* src) {
    asm volatile("cp.async.cg.shared.global [%0], [%1], 16;" :: "r"(dst), "l"(src) : "memory");
}
__device__ __forceinline__ void cpa_commit() {
    asm volatile("cp.async.commit_group;" ::: "memory");
}
__device__ __forceinline__ void cpa_wait1() {
    asm volatile("cp.async.wait_group 1;" ::: "memory");
}

__global__ void __launch_bounds__(NTH)
prep_kernel(const float* __restrict__ kin, const float* __restrict__ src,
            const float* __restrict__ dst)
{
    int gid = blockIdx.x * NTH + threadIdx.x;
    int rowg = gid >> 2;
    int q = gid & 3;
    float s = sqrtf(src[rowg] + 1e-12f);
    float d = sqrtf(dst[rowg] + 1e-12f);
    const float* kp = kin + (size_t)rowg * D_DIM + q * 16;
    const size_t rbase = (size_t)rowg * D_DIM;

    #pragma unroll
    for (int g = 0; g < 2; ++g) {
        float4 v0 = *(const float4*)(kp + g * 8);
        float4 v1 = *(const float4*)(kp + g * 8 + 4);
        __half2 a0 = __floats2half2_rn(v0.x * s, v0.y * s);
        __half2 a1 = __floats2half2_rn(v0.z * s, v0.w * s);
        __half2 a2 = __floats2half2_rn(v1.x * s, v1.y * s);
        __half2 a3 = __floats2half2_rn(v1.z * s, v1.w * s);
        __half2 b0 = __floats2half2_rn(v0.x * d, v0.y * d);
        __half2 b1 = __floats2half2_rn(v0.z * d, v0.w * d);
        __half2 b2 = __floats2half2_rn(v1.x * d, v1.y * d);
        __half2 b3 = __floats2half2_rn(v1.z * d, v1.w * d);
        int edst = q * 16 + g * 8;
        *(uint4*)(g_A + rbase + edst) = make_uint4(*(uint32_t*)&a0, *(uint32_t*)&a1,
                                                   *(uint32_t*)&a2, *(uint32_t*)&a3);
        *(uint4*)(g_B + rbase + edst) = make_uint4(*(uint32_t*)&b0, *(uint32_t*)&b1,
                                                   *(uint32_t*)&b2, *(uint32_t*)&b3);
    }
}

__device__ __forceinline__ void copyB(uint32_t sbase, int buf, size_t bbase, int jt, int tid)
{
    #pragma unroll
    for (int it = 0; it < 4; ++it) {
        int idx = tid + it * NTH;
        int rowp = idx >> 3, seg = idx & 7;
        int grp = rowp >> 4;
        int p = rowp & 15;
        int u = p >> 3, w = p & 7;
        int l = (w >> 1) * 4 + u * 2 + (w & 1);
        int srow = jt * JT + grp * 16 + l;
        uint32_t dst = (uint32_t)(rowp * 128 + ((seg * 16) ^ ((rowp & 7) << 4)));
        cpa16(sbase + OFF_B(buf) + dst, g_B + bbase + (size_t)srow * D_DIM + seg * 8);
    }
}

template <bool MASK>
__device__ __forceinline__ void half_epilogue(
    const float (*acc)[4], int ci,
    float& carry, float* rowp, int jbase, int irow, int q)
{
    const unsigned F = 0xffffffffu;
    float x0[4], p1[4], p2[4], p3[4], sc[4], C[4];
    #pragma unroll
    for (int g = 0; g < 4; ++g) {
        float y0 = pow23(acc[2 * g][ci]);
        float y1 = pow23(acc[2 * g][ci + 1]);
        float y2 = pow23(acc[2 * g + 1][ci]);
        float y3 = pow23(acc[2 * g + 1][ci + 1]);
        x0[g] = y0;
        p1[g] = y0 + y1;
        p2[g] = p1[g] + y2;
        p3[g] = p2[g] + y3;
        sc[g] = p3[g];
    }
    #pragma unroll
    for (int g = 0; g < 4; ++g) {
        float s1 = __shfl_up_sync(F, sc[g], 1, 4); if (q >= 1) sc[g] += s1;
        float s2 = __shfl_up_sync(F, sc[g], 2, 4); if (q >= 2) sc[g] += s2;
    }
    #pragma unroll
    for (int g = 0; g < 4; ++g)
        C[g] = __shfl_sync(F, sc[g], 3, 4);
    float base = carry;
    #pragma unroll
    for (int g = 0; g < 4; ++g) {
        const int cq = jbase + g * 16 + q * 4;
        float b = base + (sc[g] - p3[g]);
        float4 o;
        if (MASK) {
            o.x = (cq     >= irow) ? b + x0[g] : 0.0f;
            o.y = (cq + 1 >= irow) ? b + p1[g] : 0.0f;
            o.z = (cq + 2 >= irow) ? b + p2[g] : 0.0f;
            o.w = (cq + 3 >= irow) ? b + p3[g] : 0.0f;
        } else {
            o.x = b + x0[g]; o.y = b + p1[g]; o.z = b + p2[g]; o.w = b + p3[g];
        }
        __stcs((float4*)(rowp + cq), o);
        base += C[g];
    }
    carry = base;
}

__global__ void __launch_bounds__(NTH, 4)
mha_fp16(float* __restrict__ out)
{
    extern __shared__ char smem[];
    const uint32_t sbase = smem_u32(smem);
    const int tid = threadIdx.x;
    const int warp = tid >> 5;
    const int lane = tid & 31;
    const int q = lane & 3;

    // Load-balanced bid -> (bxe, bh): residues r<68 host 4 CTAs (give them the
    // 272 lightest = high-bxe work items, layer-spread); r>=68 host 3 CTAs
    // (240 heaviest = low-bxe). Same-residue CTAs share an SM (classic LUT).
    const int bid = blockIdx.x;
    const int r = bid % 148;
    const int l = bid / 148;
    const int s = (r >= 68) ? (r - 68 + 80 * l) : (240 + r + 68 * l);
    const int bxe = s >> 5;
    const int bh = s & 31;
    const int i0 = bxe * ROWS;

    const size_t khead = (size_t)bh * L_DIM * D_DIM;
    const size_t abase = khead + (size_t)i0 * D_DIM;
    const size_t bbase = khead;

    #pragma unroll
    for (int it = 0; it < 4; ++it) {
        int idx = tid + it * NTH;
        int row = idx >> 3, seg = idx & 7;
        uint32_t dst = (uint32_t)(row * 128 + ((seg * 16) ^ ((row & 7) << 4)));
        cpa16(sbase + OFF_A + dst, g_A + abase + (size_t)row * D_DIM + seg * 8);
    }
    copyB(sbase, 0, bbase, 0, tid);
    cpa_commit();
    copyB(sbase, 1, bbase, 1, tid);
    cpa_commit();

    const int rb = warp * 16;
    const int rming = i0 + rb;
    const int dt = i0 >> 7;
    const int ar0 = rb + ((lane >> 3) & 1) * 8 + (lane & 7);
    const int a_kb = ((lane >> 4) & 1) * 16;
    const int ax   = (ar0 & 7) << 4;
    const int br   = ((lane >> 4) & 1) * 8 + (lane & 7);
    const int b_kb = ((lane >> 3) & 1) * 16;
    const int bx2  = (br & 7) << 4;

    cpa_wait1();
    __syncthreads();

    uint32_t afr[4][4];
    #pragma unroll
    for (int ks = 0; ks < 4; ++ks)
        ldsm4(afr[ks], sbase + OFF_A + ar0 * 128 + (((ks * 32) | a_kb) ^ ax));

    const int iu = rming + (lane >> 2);
    const int idn = iu + 8;
    float* const oru_base = out + ((size_t)bh * L_DIM + iu) * L_DIM;
    float* const ord_base = oru_base + 8 * L_DIM;

    float c_up = 0.0f, c_dn = 0.0f;

    for (int jt = 0; jt < NJT; ++jt) {
        if (jt) { cpa_wait1(); __syncthreads(); }
        const uint32_t B = sbase + OFF_B(jt & 1);
        const bool zt = (jt < dt);
        const bool mt = (jt == dt);
        float zu = 0.f, zd = 0.f;

        #pragma unroll
        for (int h = 0; h < 2; ++h) {
            float acc[8][4];
            #pragma unroll
            for (int n = 0; n < 8; ++n)
                #pragma unroll
                for (int c = 0; c < 4; ++c) acc[n][c] = 0.0f;

            #pragma unroll
            for (int ks = 0; ks < 4; ++ks) {
                const int kb2 = ((ks * 32) | b_kb) ^ bx2;
                #pragma unroll
                for (int cgl = 0; cgl < 4; ++cgl) {
                    const int cg = h * 4 + cgl;
                    uint32_t bf[4];
                    ldsm4(bf, B + (uint32_t)((cg * 16 + br) * 128 + kb2));
                    mma16816(acc[2 * cgl],     afr[ks], bf);
                    mma16816(acc[2 * cgl + 1], afr[ks], bf + 2);
                }
            }

            if (h == 1) {
                __syncthreads();
                if (jt + 2 < NJT) copyB(sbase, jt & 1, bbase, jt + 2, tid);
                cpa_commit();
            }

            if (zt) {
                #pragma unroll
                for (int nb = 0; nb < 8; ++nb) {
                    zu += pow23(acc[nb][0]) + pow23(acc[nb][1]);
                    zd += pow23(acc[nb][2]) + pow23(acc[nb][3]);
                }
            } else {
                const int jbase = jt * JT + h * 64;
                if (mt) {
                    half_epilogue<true>(acc, 0, c_up, oru_base, jbase, iu, q);
                    half_epilogue<true>(acc, 2, c_dn, ord_base, jbase, idn, q);
                } else {
                    half_epilogue<false>(acc, 0, c_up, oru_base, jbase, iu, q);
                    half_epilogue<false>(acc, 2, c_dn, ord_base, jbase, idn, q);
                }
            }
        }

        if (zt) {
            float t = zu;
            t += __shfl_xor_sync(0xffffffffu, t, 1, 4);
            t += __shfl_xor_sync(0xffffffffu, t, 2, 4);
            c_up += t;
            float s2 = zd;
            s2 += __shfl_xor_sync(0xffffffffu, s2, 1, 4);
            s2 += __shfl_xor_sync(0xffffffffu, s2, 2, 4);
            c_dn += s2;
            float4 z4 = make_float4(0.f, 0.f, 0.f, 0.f);
            float* obase = out + ((size_t)bh * L_DIM + rming) * L_DIM + jt * JT + lane * 4;
            #pragma unroll 4
            for (int rr = 0; rr < 16; ++rr)
                __stcs((float4*)(obase + (size_t)rr * L_DIM), z4);
        }
    }
}

extern "C" void kernel_launch(void* const* d_in, const int* in_sizes, int n_in,
                              void* d_out, int out_size) {
    const float* k    = (const float*)d_in[0];
    const float* src  = (const float*)d_in[1];
    const float* dest = (const float*)d_in[2];
    float* out = (float*)d_out;

    prep_kernel<<<(N_BH * L_DIM * 4) / NTH, NTH>>>(k, src, dest);

    cudaFuncSetAttribute(mha_fp16,
                         cudaFuncAttributeMaxDynamicSharedMemorySize, SMEM_TOTAL);
    mha_fp16<<<512, NTH, SMEM_TOTAL>>>(out);
}